// round 2
// baseline (speedup 1.0000x reference)
#include <cuda_runtime.h>
#include <math.h>
#include <stdint.h>

// Problem constants
#define BQ    512
#define EDIM  512
#define CDIM  70722
#define TWC   (2*CDIM)
#define EPSF  0.001f
#define HF    0.333f
#define SF    64.0f
#define MMARG 0.4f
#define TALPHA 1.0f

// Scratch (no dynamic allocation allowed)
__device__ float d_invn0[CDIM];   // 1/||kernel[:,0,c]||
__device__ float d_cos2t[BQ];     // clipped cosine[b,1,label[b]]
__device__ float d_gang[BQ];      // -M*margin_scaler
__device__ float d_gadd[BQ];      // M + M*margin_scaler

// ---------------------------------------------------------------------------
// K1: column norms of the t=0 plane. Reads 145 MB. 8 accumulators for MLP.
// ---------------------------------------------------------------------------
__global__ void colnorm_kernel(const float* __restrict__ kern) {
    int c = blockIdx.x * 256 + threadIdx.x;
    if (c >= CDIM) return;
    const float* p = kern + c;
    float s0=0.f,s1=0.f,s2=0.f,s3=0.f,s4=0.f,s5=0.f,s6=0.f,s7=0.f;
    for (int e = 0; e < EDIM; e += 8) {
        float v0 = p[(size_t)(e+0)*TWC];
        float v1 = p[(size_t)(e+1)*TWC];
        float v2 = p[(size_t)(e+2)*TWC];
        float v3 = p[(size_t)(e+3)*TWC];
        float v4 = p[(size_t)(e+4)*TWC];
        float v5 = p[(size_t)(e+5)*TWC];
        float v6 = p[(size_t)(e+6)*TWC];
        float v7 = p[(size_t)(e+7)*TWC];
        s0 += v0*v0; s1 += v1*v1; s2 += v2*v2; s3 += v3*v3;
        s4 += v4*v4; s5 += v5*v5; s6 += v6*v6; s7 += v7*v7;
    }
    d_invn0[c] = rsqrtf(((s0+s1)+(s2+s3)) + ((s4+s5)+(s6+s7)));
}

// ---------------------------------------------------------------------------
// K2: cos2_tgt[b] = clip( <emb[b,:], k1[:,label[b]]> / ||k1[:,label[b]]|| )
// One block (128 thr) per batch row. Tiny.
// ---------------------------------------------------------------------------
__global__ void cos2_kernel(const float* __restrict__ kern,
                            const float* __restrict__ emb,
                            const int*   __restrict__ label) {
    int b = blockIdx.x;
    int t = threadIdx.x;
    int lab = label[b];
    const float* col = kern + (size_t)CDIM + lab;  // t=1 plane
    float ss = 0.f, dt = 0.f;
    for (int e = t; e < EDIM; e += 128) {
        float v = col[(size_t)e * TWC];
        ss += v * v;
        dt += emb[b * EDIM + e] * v;
    }
    __shared__ float sss[128], sdt[128];
    sss[t] = ss; sdt[t] = dt;
    __syncthreads();
    for (int o = 64; o > 0; o >>= 1) {
        if (t < o) { sss[t] += sss[t+o]; sdt[t] += sdt[t+o]; }
        __syncthreads();
    }
    if (t == 0) {
        float cz = sdt[0] * rsqrtf(sss[0]);
        cz = fminf(fmaxf(cz, -1.0f + EPSF), 1.0f - EPSF);
        d_cos2t[b] = cz;
    }
}

// ---------------------------------------------------------------------------
// K3: batch statistics + per-row margin coefficients + cw_margin output.
// Single block of 512 threads; classwise mean via O(B^2) smem scan.
// ---------------------------------------------------------------------------
__global__ void stats_kernel(const float* __restrict__ norms,
                             const int*   __restrict__ label,
                             float* __restrict__ out) {
    __shared__ float sn[BQ];
    __shared__ int   lab[BQ];
    __shared__ float red[BQ];
    int t = threadIdx.x;
    float x = norms[t];
    x = fminf(fmaxf(x, 0.001f), 100.0f);
    sn[t] = x; lab[t] = label[t];
    red[t] = x;
    __syncthreads();
    for (int o = 256; o > 0; o >>= 1) {
        if (t < o) red[t] += red[t+o];
        __syncthreads();
    }
    float mean = red[0] * (1.0f / BQ);
    __syncthreads();
    float d = x - mean;
    red[t] = d * d;
    __syncthreads();
    for (int o = 256; o > 0; o >>= 1) {
        if (t < o) red[t] += red[t+o];
        __syncthreads();
    }
    float stdv = sqrtf(red[0] / (float)(BQ - 1));

    float batch_mean = mean * TALPHA + (1.0f - TALPHA) * 20.0f;
    float batch_std  = stdv * TALPHA + (1.0f - TALPHA) * 10.0f;

    // classwise mean of sn for this row's label (count >= 1: includes self)
    int  ml = lab[t];
    float s = 0.f; int cnt = 0;
    for (int j = 0; j < BQ; ++j) {
        if (lab[j] == ml) { s += sn[j]; cnt++; }
    }
    float bgm = s / (float)cnt;
    float cwm = bgm * TALPHA + (1.0f - TALPHA) * 20.0f;

    float inv = 1.0f / (batch_std + EPSF);
    float ms = fminf(fmaxf((x - batch_mean) * inv * HF, -1.0f), 1.0f);
    d_gang[t] = -MMARG * ms;
    d_gadd[t] =  MMARG + MMARG * ms;
    out[(size_t)2 * BQ * CDIM + t] =
        fminf(fmaxf((x - cwm) * inv, -1.0f), 1.0f) * HF;
}

// ---------------------------------------------------------------------------
// K4: main GEMM + epilogue.
// out1[b,c] = out2[b,c] = 64 * clip( <emb[b,:],k0[:,c]> * invn0[c] )
// BM=128, BN=128, BK=16, 256 threads, 8x8 per-thread tile.
// Grid: x = 4 M-tiles (fast) so same-column-tile blocks share k0 in L2.
// ---------------------------------------------------------------------------
__global__ __launch_bounds__(256, 2)
void gemm_kernel(const float* __restrict__ A,       // emb [512,512]
                 const float* __restrict__ Kn,      // kernel base (t=0 plane at stride TWC)
                 float* __restrict__ out) {
    __shared__ float As[16][128];
    __shared__ float Bs[16][128];
    const int t = threadIdx.x;
    const int mbase = blockIdx.x * 128;
    const int cbase = blockIdx.y * 128;
    const int tm = (t >> 4) * 8;
    const int tn = (t & 15) * 8;

    float acc[8][8];
    #pragma unroll
    for (int i = 0; i < 8; ++i)
        #pragma unroll
        for (int j = 0; j < 8; ++j) acc[i][j] = 0.f;

    for (int kb = 0; kb < EDIM; kb += 16) {
        // A tile: 128x16, 2 float4 per thread, transposed into As[k][m]
        #pragma unroll
        for (int i = 0; i < 2; ++i) {
            int u  = t + i * 256;          // 0..511
            int m  = u >> 2;               // 0..127
            int kq = (u & 3) << 2;         // 0,4,8,12
            const float4 v = *(const float4*)&A[(size_t)(mbase + m) * EDIM + kb + kq];
            As[kq+0][m] = v.x; As[kq+1][m] = v.y;
            As[kq+2][m] = v.z; As[kq+3][m] = v.w;
        }
        // B tile: 16x128, 8 guarded scalars per thread, coalesced over c
        #pragma unroll
        for (int i = 0; i < 8; ++i) {
            int u = t + i * 256;           // 0..2047
            int e = u >> 7;                // 0..15
            int n = u & 127;
            int c = cbase + n;
            Bs[e][n] = (c < CDIM) ? Kn[(size_t)(kb + e) * TWC + c] : 0.0f;
        }
        __syncthreads();
        #pragma unroll
        for (int k = 0; k < 16; ++k) {
            float4 a0 = *(const float4*)&As[k][tm];
            float4 a1 = *(const float4*)&As[k][tm + 4];
            float4 b0 = *(const float4*)&Bs[k][tn];
            float4 b1 = *(const float4*)&Bs[k][tn + 4];
            float ra[8] = {a0.x,a0.y,a0.z,a0.w,a1.x,a1.y,a1.z,a1.w};
            float rb[8] = {b0.x,b0.y,b0.z,b0.w,b1.x,b1.y,b1.z,b1.w};
            #pragma unroll
            for (int i = 0; i < 8; ++i)
                #pragma unroll
                for (int j = 0; j < 8; ++j)
                    acc[i][j] += ra[i] * rb[j];
        }
        __syncthreads();
    }

    // Epilogue
    float inv[8];
    #pragma unroll
    for (int j = 0; j < 8; ++j) {
        int c = cbase + tn + j;
        inv[j] = (c < CDIM) ? d_invn0[c] : 1.0f;
    }
    const float lo = -1.0f + EPSF, hi = 1.0f - EPSF;
    const bool full = (cbase + 128 <= CDIM);
    #pragma unroll
    for (int i = 0; i < 8; ++i) {
        int r = mbase + tm + i;
        float v[8];
        #pragma unroll
        for (int j = 0; j < 8; ++j) {
            float x = acc[i][j] * inv[j];
            x = fminf(fmaxf(x, lo), hi);
            v[j] = x * SF;
        }
        size_t base = (size_t)r * CDIM + cbase + tn;
        float* o1 = out + base;
        float* o2 = out + (size_t)BQ * CDIM + base;
        if (full) {
            #pragma unroll
            for (int j = 0; j < 8; j += 2) {
                float2 p = make_float2(v[j], v[j+1]);
                *(float2*)(o1 + j) = p;
                *(float2*)(o2 + j) = p;
            }
        } else {
            #pragma unroll
            for (int j = 0; j < 8; ++j) {
                if (cbase + tn + j < CDIM) { o1[j] = v[j]; o2[j] = v[j]; }
            }
        }
    }
}

// ---------------------------------------------------------------------------
// K5: label-column fixup. Overwrites out1/out2 at (b, label[b]) with the
// full margin formula. Runs after K4 (stream-ordered).
// ---------------------------------------------------------------------------
__global__ void fixup_kernel(const float* __restrict__ kern,
                             const float* __restrict__ emb,
                             const int*   __restrict__ label,
                             float* __restrict__ out) {
    int b = blockIdx.x;
    int t = threadIdx.x;
    int lab = label[b];
    const float* col = kern + lab;  // t=0 plane
    float dt = 0.f;
    for (int e = t; e < EDIM; e += 128)
        dt += emb[b * EDIM + e] * col[(size_t)e * TWC];
    __shared__ float sdt[128];
    sdt[t] = dt;
    __syncthreads();
    for (int o = 64; o > 0; o >>= 1) {
        if (t < o) sdt[t] += sdt[t+o];
        __syncthreads();
    }
    if (t == 0) {
        const float lo = -1.0f + EPSF, hi = 1.0f - EPSF;
        const float thlo = EPSF, thhi = (float)M_PI - EPSF;
        float gang = d_gang[b], gadd = d_gadd[b];

        float w1 = sdt[0] * d_invn0[lab];
        w1 = fminf(fmaxf(w1, lo), hi);
        float th1 = fminf(fmaxf(acosf(w1) + gang, thlo), thhi);
        out[(size_t)b * CDIM + lab] = (cosf(th1) - gadd) * SF;

        float w2 = d_cos2t[b];
        float th2 = fminf(fmaxf(acosf(w2) + gang, thlo), thhi);
        out[(size_t)BQ * CDIM + (size_t)b * CDIM + lab] = (cosf(th2) - gadd) * SF;
    }
}

// ---------------------------------------------------------------------------
extern "C" void kernel_launch(void* const* d_in, const int* in_sizes, int n_in,
                              void* d_out, int out_size) {
    const float* emb   = (const float*)d_in[0];  // [512, 512]
    const float* norms = (const float*)d_in[1];  // [512, 1]
    const int*   label = (const int*)  d_in[2];  // [512]
    const float* kern  = (const float*)d_in[3];  // [512, 2, 70722]
    float* out = (float*)d_out;

    colnorm_kernel<<<(CDIM + 255) / 256, 256>>>(kern);
    cos2_kernel<<<BQ, 128>>>(kern, emb, label);
    stats_kernel<<<1, BQ>>>(norms, label, out);
    gemm_kernel<<<dim3(4, (CDIM + 127) / 128), 256>>>(emb, kern, out);
    fixup_kernel<<<BQ, 128>>>(kern, emb, label, out);
}